// round 1
// baseline (speedup 1.0000x reference)
#include <cuda_runtime.h>
#include <cuda_bf16.h>
#include <stdint.h>

// Problem constants (hidden dim is structural; counts taken from in_sizes).
#define D 64
#define MAXREL 50

// Small precomputed tables (device globals: no runtime allocation allowed).
__device__ float g_P[MAXREL * D];              // rel_emb @ W_msg[0:64]
__device__ float g_Q[MAXREL * D];              // rel_emb @ W_msg[64:128]
__device__ float g_base[MAXREL * D];           // rel_emb @ W_upd[0:64]
__device__ float g_M2[MAXREL * MAXREL * D];    // relu(P[r1]+Q[r2]) @ W_upd[64:128]

// ---------------------------------------------------------------------------
// Kernel A1: per-relation projections P, Q, base.  grid = NUM_REL, block = 64.
// ---------------------------------------------------------------------------
__global__ void build_pq_base(const float* __restrict__ rel_emb,
                              const float* __restrict__ W_msg,
                              const float* __restrict__ W_upd) {
    __shared__ float sh_e[D];
    const int r = blockIdx.x;
    const int j = threadIdx.x;
    sh_e[j] = rel_emb[r * D + j];
    __syncthreads();
    float p = 0.f, q = 0.f, b = 0.f;
#pragma unroll
    for (int k = 0; k < D; k++) {
        const float e = sh_e[k];
        p = fmaf(e, W_msg[k * D + j], p);
        q = fmaf(e, W_msg[(D + k) * D + j], q);
        b = fmaf(e, W_upd[k * D + j], b);
    }
    g_P[r * D + j] = p;
    g_Q[r * D + j] = q;
    g_base[r * D + j] = b;
}

// ---------------------------------------------------------------------------
// Kernel A2: M2 table.  grid = NUM_REL*NUM_REL, block = 64.
// M2[r1,r2][j] = sum_i relu(P[r1][i] + Q[r2][i]) * W_upd[(64+i)][j]
// ---------------------------------------------------------------------------
__global__ void build_m2(const float* __restrict__ W_upd, int num_rel) {
    __shared__ float m[D];
    const int pair = blockIdx.x;
    const int r1 = pair / num_rel;
    const int r2 = pair % num_rel;
    const int j = threadIdx.x;
    m[j] = fmaxf(g_P[r1 * D + j] + g_Q[r2 * D + j], 0.f);
    __syncthreads();
    float acc = 0.f;
#pragma unroll
    for (int i = 0; i < D; i++) {
        acc = fmaf(m[i], W_upd[(D + i) * D + j], acc);
    }
    g_M2[pair * D + j] = acc;
}

// ---------------------------------------------------------------------------
// Kernel B: init out[e][:] = base[rel[e]][:].  One float4 per thread.
// total threads = E * 16.
// ---------------------------------------------------------------------------
__global__ void init_out(float4* __restrict__ out,
                         const int* __restrict__ rel,
                         long long total4) {
    long long i = (long long)blockIdx.x * blockDim.x + threadIdx.x;
    if (i >= total4) return;
    const long long e = i >> 4;
    const int j4 = (int)(i & 15);
    const int r = __ldg(&rel[e]);
    const float4* base4 = reinterpret_cast<const float4*>(g_base);
    out[i] = base4[r * 16 + j4];
}

// ---------------------------------------------------------------------------
// Kernel C: triangle scatter. One warp handles 2 triangles (16 lanes each).
// Each lane does one red.global.add.v4.f32 of the M2 row onto out[edge_ac].
// ---------------------------------------------------------------------------
__global__ void scatter_tri(float* __restrict__ out,
                            const int* __restrict__ rel,
                            const int* __restrict__ edge_ab,
                            const int* __restrict__ edge_bc,
                            const int* __restrict__ edge_ac,
                            long long num_tri, int num_rel) {
    const long long warp = ((long long)blockIdx.x * blockDim.x + threadIdx.x) >> 5;
    const int lane = threadIdx.x & 31;
    const int half = lane >> 4;   // which of the 2 triangles
    const int hl = lane & 15;     // lane within half (covers 4 floats)

    const long long t = warp * 2 + half;
    const bool valid = (t < num_tri);
    const long long ts = valid ? t : (num_tri - 1);  // safe clamp for loads

    int c = 0, p = 0;
    if (hl == 0) {
        const int a = __ldg(&edge_ab[ts]);
        const int b = __ldg(&edge_bc[ts]);
        c = __ldg(&edge_ac[ts]);
        const int ra = __ldg(&rel[a]);
        const int rb = __ldg(&rel[b]);
        p = ra * num_rel + rb;
    }
    // broadcast from the leader lane of each half
    c = __shfl_sync(0xffffffffu, c, half * 16);
    p = __shfl_sync(0xffffffffu, p, half * 16);

    if (valid) {
        const float4 v =
            *reinterpret_cast<const float4*>(&g_M2[(long long)p * D + hl * 4]);
        float* dst = &out[(long long)c * D + hl * 4];
        asm volatile("red.global.add.v4.f32 [%0], {%1,%2,%3,%4};"
                     :: "l"(dst), "f"(v.x), "f"(v.y), "f"(v.z), "f"(v.w)
                     : "memory");
    }
}

// ---------------------------------------------------------------------------
// Kernel D: in-place relu over the output.
// ---------------------------------------------------------------------------
__global__ void relu_out(float4* __restrict__ out, long long total4) {
    long long i = (long long)blockIdx.x * blockDim.x + threadIdx.x;
    if (i >= total4) return;
    float4 v = out[i];
    v.x = fmaxf(v.x, 0.f);
    v.y = fmaxf(v.y, 0.f);
    v.z = fmaxf(v.z, 0.f);
    v.w = fmaxf(v.w, 0.f);
    out[i] = v;
}

// ---------------------------------------------------------------------------
// Inputs (metadata order): rel_emb, W_msg, W_upd, src, dst, rel,
//                          edge_ab, edge_bc, edge_ac
// ---------------------------------------------------------------------------
extern "C" void kernel_launch(void* const* d_in, const int* in_sizes, int n_in,
                              void* d_out, int out_size) {
    const float* rel_emb = (const float*)d_in[0];
    const float* W_msg   = (const float*)d_in[1];
    const float* W_upd   = (const float*)d_in[2];
    const int*   rel     = (const int*)d_in[5];
    const int*   edge_ab = (const int*)d_in[6];
    const int*   edge_bc = (const int*)d_in[7];
    const int*   edge_ac = (const int*)d_in[8];

    const int num_rel = in_sizes[0] / D;        // 50
    const long long num_edge = in_sizes[5];     // 1,000,000
    const long long num_tri  = in_sizes[6];     // 2,000,000

    float* out = (float*)d_out;

    // A1 + A2: tiny table builds
    build_pq_base<<<num_rel, D>>>(rel_emb, W_msg, W_upd);
    build_m2<<<num_rel * num_rel, D>>>(W_upd, num_rel);

    // B: init out with base[rel[e]]
    const long long total4 = num_edge * (D / 4);
    {
        const int threads = 256;
        const long long blocks = (total4 + threads - 1) / threads;
        init_out<<<(unsigned)blocks, threads>>>((float4*)out, rel, total4);
    }

    // C: scatter triangle messages (2 triangles per warp)
    {
        const int threads = 256;
        const long long warps = (num_tri + 1) / 2;
        const long long blocks = (warps * 32 + threads - 1) / threads;
        scatter_tri<<<(unsigned)blocks, threads>>>(out, rel, edge_ab, edge_bc,
                                                   edge_ac, num_tri, num_rel);
    }

    // D: final relu in place
    {
        const int threads = 256;
        const long long blocks = (total4 + threads - 1) / threads;
        relu_out<<<(unsigned)blocks, threads>>>((float4*)out, total4);
    }
}

// round 2
// speedup vs baseline: 1.8171x; 1.8171x over previous
#include <cuda_runtime.h>
#include <cuda_bf16.h>
#include <stdint.h>

#define D 64
#define MAXREL 50
#define NE_MAX 1100000
#define NT_MAX 2200000

// Precomputed tables.
__device__ float g_P[MAXREL * D];              // rel_emb @ W_msg[0:64]
__device__ float g_Q[MAXREL * D];              // rel_emb @ W_msg[64:128]
__device__ float g_base[MAXREL * D];           // rel_emb @ W_upd[0:64]
__device__ float g_M2[MAXREL * MAXREL * D];    // relu(P[r1]+Q[r2]) @ W_upd[64:128]

// Sort scratch (device globals — no runtime allocation allowed).
__device__ int g_cur[NE_MAX];                  // count, then write cursor, ends as segment end
__device__ int g_start[NE_MAX];                // segment start
__device__ unsigned short g_tmp_pair[NT_MAX];  // per-triangle pair idx
__device__ unsigned short g_sorted_pair[NT_MAX];
__device__ int g_cursor;

// ---------------------------------------------------------------------------
// Zero per-call state (graph replays reuse device globals).
// ---------------------------------------------------------------------------
__global__ void zero_state(int num_edge) {
    int i = blockIdx.x * blockDim.x + threadIdx.x;
    if (i < num_edge) g_cur[i] = 0;
    if (i == 0) g_cursor = 0;
}

// ---------------------------------------------------------------------------
// Tables: P, Q, base per relation.  grid = NUM_REL, block = 64.
// ---------------------------------------------------------------------------
__global__ void build_pq_base(const float* __restrict__ rel_emb,
                              const float* __restrict__ W_msg,
                              const float* __restrict__ W_upd) {
    __shared__ float sh_e[D];
    const int r = blockIdx.x;
    const int j = threadIdx.x;
    sh_e[j] = rel_emb[r * D + j];
    __syncthreads();
    float p = 0.f, q = 0.f, b = 0.f;
#pragma unroll
    for (int k = 0; k < D; k++) {
        const float e = sh_e[k];
        p = fmaf(e, W_msg[k * D + j], p);
        q = fmaf(e, W_msg[(D + k) * D + j], q);
        b = fmaf(e, W_upd[k * D + j], b);
    }
    g_P[r * D + j] = p;
    g_Q[r * D + j] = q;
    g_base[r * D + j] = b;
}

// M2[r1,r2][j] = sum_i relu(P[r1][i]+Q[r2][i]) * W_upd[64+i][j]
__global__ void build_m2(const float* __restrict__ W_upd, int num_rel) {
    __shared__ float m[D];
    const int pair = blockIdx.x;
    const int r1 = pair / num_rel;
    const int r2 = pair % num_rel;
    const int j = threadIdx.x;
    m[j] = fmaxf(g_P[r1 * D + j] + g_Q[r2 * D + j], 0.f);
    __syncthreads();
    float acc = 0.f;
#pragma unroll
    for (int i = 0; i < D; i++) {
        acc = fmaf(m[i], W_upd[(D + i) * D + j], acc);
    }
    g_M2[pair * D + j] = acc;
}

// ---------------------------------------------------------------------------
// Pass 1: per triangle — pair index + histogram of head edges.
// ---------------------------------------------------------------------------
__global__ void tri_count(const int* __restrict__ rel,
                          const int* __restrict__ edge_ab,
                          const int* __restrict__ edge_bc,
                          const int* __restrict__ edge_ac,
                          int num_tri, int num_rel) {
    int t = blockIdx.x * blockDim.x + threadIdx.x;
    if (t >= num_tri) return;
    const int a = __ldg(&edge_ab[t]);
    const int b = __ldg(&edge_bc[t]);
    const int c = __ldg(&edge_ac[t]);
    const int p = __ldg(&rel[a]) * num_rel + __ldg(&rel[b]);
    g_tmp_pair[t] = (unsigned short)p;
    atomicAdd(&g_cur[c], 1);
}

// ---------------------------------------------------------------------------
// Pass 2: allocate contiguous segments.  Block-local exclusive scan +
// one global atomic per block (segment placement order is irrelevant).
// ---------------------------------------------------------------------------
__global__ void alloc_segments(int num_edge) {
    __shared__ int sh[256];
    __shared__ int blk_base;
    const int t = threadIdx.x;
    const int e = blockIdx.x * 256 + t;
    const int c = (e < num_edge) ? g_cur[e] : 0;
    sh[t] = c;
    __syncthreads();
#pragma unroll
    for (int off = 1; off < 256; off <<= 1) {
        int v = (t >= off) ? sh[t - off] : 0;
        __syncthreads();
        sh[t] += v;
        __syncthreads();
    }
    if (t == 255) blk_base = atomicAdd(&g_cursor, sh[255]);
    __syncthreads();
    if (e < num_edge) {
        const int s = blk_base + sh[t] - c;   // exclusive
        g_start[e] = s;
        g_cur[e] = s;                         // becomes write cursor
    }
}

// ---------------------------------------------------------------------------
// Pass 3: place pair indices into their edge's segment.
// ---------------------------------------------------------------------------
__global__ void tri_place(const int* __restrict__ edge_ac, int num_tri) {
    int t = blockIdx.x * blockDim.x + threadIdx.x;
    if (t >= num_tri) return;
    const int c = __ldg(&edge_ac[t]);
    const int pos = atomicAdd(&g_cur[c], 1);
    g_sorted_pair[pos] = g_tmp_pair[t];
}

// ---------------------------------------------------------------------------
// Pass 4: per edge — sum segment's M2 rows + base[rel[e]], relu, write once.
// One half-warp (16 lanes x float4) per edge.
// ---------------------------------------------------------------------------
__global__ void finalize(float4* __restrict__ out,
                         const int* __restrict__ rel,
                         int num_edge) {
    const int e = blockIdx.x * (blockDim.x >> 4) + (threadIdx.x >> 4);
    const int hl = threadIdx.x & 15;
    if (e >= num_edge) return;

    const int s  = g_start[e];
    const int en = g_cur[e];          // end after pass 3
    const int r  = __ldg(&rel[e]);

    const float4* base4 = reinterpret_cast<const float4*>(g_base);
    const float4* m2_4  = reinterpret_cast<const float4*>(g_M2);

    float4 acc = base4[r * 16 + hl];
    for (int i = s; i < en; i++) {
        const int p = g_sorted_pair[i];
        const float4 v = m2_4[p * 16 + hl];
        acc.x += v.x; acc.y += v.y; acc.z += v.z; acc.w += v.w;
    }
    acc.x = fmaxf(acc.x, 0.f);
    acc.y = fmaxf(acc.y, 0.f);
    acc.z = fmaxf(acc.z, 0.f);
    acc.w = fmaxf(acc.w, 0.f);
    out[e * 16 + hl] = acc;
}

// ---------------------------------------------------------------------------
// Inputs: rel_emb, W_msg, W_upd, src, dst, rel, edge_ab, edge_bc, edge_ac
// ---------------------------------------------------------------------------
extern "C" void kernel_launch(void* const* d_in, const int* in_sizes, int n_in,
                              void* d_out, int out_size) {
    const float* rel_emb = (const float*)d_in[0];
    const float* W_msg   = (const float*)d_in[1];
    const float* W_upd   = (const float*)d_in[2];
    const int*   rel     = (const int*)d_in[5];
    const int*   edge_ab = (const int*)d_in[6];
    const int*   edge_bc = (const int*)d_in[7];
    const int*   edge_ac = (const int*)d_in[8];

    const int num_rel  = in_sizes[0] / D;   // 50
    const int num_edge = in_sizes[5];       // 1,000,000
    const int num_tri  = in_sizes[6];       // 2,000,000

    float4* out = (float4*)d_out;

    zero_state<<<(num_edge + 255) / 256, 256>>>(num_edge);
    build_pq_base<<<num_rel, D>>>(rel_emb, W_msg, W_upd);
    build_m2<<<num_rel * num_rel, D>>>(W_upd, num_rel);

    tri_count<<<(num_tri + 255) / 256, 256>>>(rel, edge_ab, edge_bc, edge_ac,
                                              num_tri, num_rel);
    alloc_segments<<<(num_edge + 255) / 256, 256>>>(num_edge);
    tri_place<<<(num_tri + 255) / 256, 256>>>(edge_ac, num_tri);

    finalize<<<(num_edge * 16 + 255) / 256, 256>>>(out, rel, num_edge);
}